// round 5
// baseline (speedup 1.0000x reference)
#include <cuda_runtime.h>

// QuantumConvLayer: out[:,2i]   = cos(q[2i]) * cos(pi*x[:,2i])
//                   out[:,2i+1] = out[:,2i]  * cos(q[2i+1] + pi*x[:,2i+1])
// Streaming HBM-bound (256MB read + 256MB write).
// R5: 8 float4/thread, block-strided (fully coalesced), MLP=8 front-batched
// loads to deepen per-SM in-flight bytes. No tail (n4 % 2048 == 0) -> no
// predicates. Single q float4 per thread (stride 256 preserves row phase).

#ifndef QC_PI
#define QC_PI 3.14159265358979323846f
#endif

#define VPT 8   // float4s per thread
#define TPB 256 // threads per block

__global__ void __launch_bounds__(TPB)
qconv_kernel(const float4* __restrict__ x4,
             const float*  __restrict__ q,
             float4* __restrict__ out4)
{
    int base = blockIdx.x * (TPB * VPT) + threadIdx.x;

    // 8 coalesced 128-bit streaming loads, front-batched (MLP=8, 128B/thread)
    float4 v[VPT];
#pragma unroll
    for (int k = 0; k < VPT; k++)
        v[k] = __ldcs(x4 + base + k * TPB);

    // stride TPB=256 is 0 mod 4 -> all 8 elements share row phase (base & 3)
    const float4* q4 = (const float4*)q;
    float4 qa = __ldg(q4 + (base & 3));   // q[c..c+3], c = 4*(base&3)

    float ce = __cosf(qa.x);   // cos(q[c])
    float cf = __cosf(qa.z);   // cos(q[c+2])

#pragma unroll
    for (int k = 0; k < VPT; k++) {
        float ze0 = ce * __cosf(QC_PI * v[k].x);
        float zo0 = ze0 * __cosf(fmaf(QC_PI, v[k].y, qa.y));
        float ze1 = cf * __cosf(QC_PI * v[k].z);
        float zo1 = ze1 * __cosf(fmaf(QC_PI, v[k].w, qa.w));
        __stcs(out4 + base + k * TPB, make_float4(ze0, zo0, ze1, zo1));
    }
}

extern "C" void kernel_launch(void* const* d_in, const int* in_sizes, int n_in,
                              void* d_out, int out_size)
{
    const float4* x4 = (const float4*)d_in[0];
    const float*  q  = (const float*)d_in[1];
    float4* out4     = (float4*)d_out;

    int n_elems = in_sizes[0];   // B * 16 = 67108864
    int n4 = n_elems >> 2;       // 16777216 float4s, divisible by TPB*VPT=2048

    int blocks = n4 / (TPB * VPT);   // 8192, exact
    qconv_kernel<<<blocks, TPB>>>(x4, q, out4);
}